// round 1
// baseline (speedup 1.0000x reference)
#include <cuda_runtime.h>

#define B_    256
#define T_    4096
#define TWO_N 16
#define H_    64
#define P_    144
#define TBL   1024
#define TPB   256
#define CHUNKS (T_/TPB)      // 16
#define NBLK  (B_*CHUNKS)    // 4096

// Lookup table: row i holds (lat_0,dlat_0, lat_1,dlat_1, ..., lat_15,dlat_15) at t=i/TBL.
__device__ float g_table[TBL + 1][32];
__device__ float g_pd[NBLK];
__device__ float g_pp[NBLK];

// ---------------------------------------------------------------------------
// Kernel 1: tabulate latent(t) and d latent/dt on a 1025-point grid.
// lat_k(t)  = b2_k + sum_j tanh(t*W1_j + b1_j) * W2[j][k]
// dlat_k(t) = sum_j W1_j * (1 - tanh^2) * W2[j][k]
// ---------------------------------------------------------------------------
__global__ void build_table(const float* __restrict__ W1, const float* __restrict__ b1,
                            const float* __restrict__ W2, const float* __restrict__ b2) {
    int e = blockIdx.x * blockDim.x + threadIdx.x;
    if (e > TBL) return;
    float tv = (float)e / (float)TBL;
    float lat[16], dlat[16];
#pragma unroll
    for (int k = 0; k < 16; k++) { lat[k] = __ldg(b2 + k); dlat[k] = 0.f; }
    for (int j = 0; j < H_; j++) {
        float w1 = __ldg(W1 + j);
        float u  = fmaf(tv, w1, __ldg(b1 + j));
        float th = tanhf(u);
        float dh = w1 * (1.f - th * th);
#pragma unroll
        for (int k = 0; k < 16; k++) {
            float w2 = __ldg(W2 + j * 16 + k);
            lat[k]  = fmaf(th, w2, lat[k]);
            dlat[k] = fmaf(dh, w2, dlat[k]);
        }
    }
#pragma unroll
    for (int k = 0; k < 16; k++) {
        g_table[e][2 * k]     = lat[k];
        g_table[e][2 * k + 1] = dlat[k];
    }
}

// ---------------------------------------------------------------------------
// Kernel 2: main loss kernel. One block = (batch b, 256 t's).
// Phase A: 16 lanes/t cooperatively gather+lerp the two table rows (coalesced).
// Phase B: t-parallel compute of data + physics loss terms; block reduction.
// ---------------------------------------------------------------------------
__global__ __launch_bounds__(TPB) void main_kernel(
    const float* __restrict__ t_in,
    const float* __restrict__ x_target,
    const float* __restrict__ params) {

    __shared__ float s_t[TPB];
    __shared__ float s_stage[TPB][33];   // padded stride 33 -> conflict-free scalar access
    __shared__ float s_par[P_];          // [0..7]=g, [8..15]=mu, [16..79]=Pi, [80..143]=Gamma
    __shared__ float s_rd[TPB / 32], s_rp[TPB / 32];

    const int tid   = threadIdx.x;
    const int b     = blockIdx.x >> 4;   // / CHUNKS
    const int chunk = blockIdx.x & (CHUNKS - 1);
    const int t0    = chunk * TPB;

    s_t[tid] = __ldg(t_in + (size_t)b * T_ + t0 + tid);
    if (tid < P_) s_par[tid] = __ldg(params + (size_t)b * P_ + tid);
    __syncthreads();

    // ---- Phase A: staged gather ----
    const int kk = tid & 15;     // component pair index 0..15
    const int ts = tid >> 4;     // base t within the 16-wide groups
#pragma unroll
    for (int it = 0; it < 16; ++it) {
        int tcur = ts + it * 16;
        float tv = s_t[tcur];
        float p  = tv * (float)TBL;
        int   i  = (int)p;
        i = max(0, min(i, TBL - 1));
        float f = p - (float)i;
        float2 lo = __ldg((const float2*)g_table[i]     + kk);
        float2 hi = __ldg((const float2*)g_table[i + 1] + kk);
        s_stage[tcur][2 * kk]     = fmaf(f, hi.x - lo.x, lo.x);
        s_stage[tcur][2 * kk + 1] = fmaf(f, hi.y - lo.y, lo.y);
    }
    __syncthreads();

    // ---- Phase B: per-t compute ----
    float lat[16], dlat[16];
#pragma unroll
    for (int k = 0; k < 16; k++) {
        lat[k]  = s_stage[tid][2 * k];
        dlat[k] = s_stage[tid][2 * k + 1];
    }

    // observables: a = lat[0:8] ; x = relu(q - mu), q = lat[8:16]
    float x[8], dxv[8];
#pragma unroll
    for (int k = 0; k < 8; k++) {
        float s = lat[8 + k] - s_par[8 + k];
        x[k]   = fmaxf(s, 0.f);
        dxv[k] = (s > 0.f) ? dlat[8 + k] : 0.f;   // JVP of relu
    }

    float acc_d = 0.f, acc_p = 0.f;

    // data loss: (state - x_target)^2, x_target layout (B, 16, T)
    const float* xt = x_target + (size_t)b * TWO_N * T_ + t0 + tid;
#pragma unroll
    for (int k = 0; k < 16; k++) {
        float st = (k < 8) ? lat[k] : x[k - 8];
        float d  = st - __ldg(xt + (size_t)k * T_);
        acc_d = fmaf(d, d, acc_d);
    }

    // physics loss: dstate_dt - rhs
    //   da = g + Pi@x - a ; dx = (Gamma@a) * (mu - x)
#pragma unroll
    for (int k = 0; k < 8; k++) {
        float pix = 0.f, ga = 0.f;
#pragma unroll
        for (int j = 0; j < 8; j++) {
            pix = fmaf(s_par[16 + k * 8 + j], x[j],   pix);
            ga  = fmaf(s_par[80 + k * 8 + j], lat[j], ga);
        }
        float d1 = dlat[k] - (s_par[k] + pix - lat[k]);
        acc_p = fmaf(d1, d1, acc_p);
        float d2 = dxv[k] - ga * (s_par[8 + k] - x[k]);
        acc_p = fmaf(d2, d2, acc_p);
    }

    // ---- block reduction (deterministic tree) ----
#pragma unroll
    for (int o = 16; o; o >>= 1) {
        acc_d += __shfl_down_sync(0xffffffffu, acc_d, o);
        acc_p += __shfl_down_sync(0xffffffffu, acc_p, o);
    }
    const int lane = tid & 31, wid = tid >> 5;
    if (lane == 0) { s_rd[wid] = acc_d; s_rp[wid] = acc_p; }
    __syncthreads();
    if (tid == 0) {
        float sd = 0.f, sp = 0.f;
#pragma unroll
        for (int i = 0; i < TPB / 32; i++) { sd += s_rd[i]; sp += s_rp[i]; }
        g_pd[blockIdx.x] = sd;
        g_pp[blockIdx.x] = sp;
    }
}

// ---------------------------------------------------------------------------
// Kernel 3: deterministic finalize. Sums block partials (double), computes the
// tiny supervised loss, and writes the scalar output.
// ---------------------------------------------------------------------------
__global__ void finalize(const float* __restrict__ pp, const float* __restrict__ pt,
                         const float* __restrict__ icp, const float* __restrict__ ict,
                         float* __restrict__ out) {
    const int tid = threadIdx.x;
    double sd = 0.0, sp = 0.0, ss = 0.0;
    for (int i = tid; i < NBLK; i += 256) {
        sd += (double)g_pd[i];
        sp += (double)g_pp[i];
    }
    for (int i = tid; i < B_ * 160; i += 256) {
        int b = i / 160, r = i % 160;
        float d;
        if (r < P_) d = __ldg(pp + b * P_ + r) - __ldg(pt + b * P_ + r);
        else        d = __ldg(icp + b * 16 + (r - P_)) - __ldg(ict + b * 16 + (r - P_));
        ss += (double)d * (double)d;
    }
    __shared__ double r1[256], r2[256], r3[256];
    r1[tid] = sd; r2[tid] = sp; r3[tid] = ss;
    __syncthreads();
    for (int o = 128; o; o >>= 1) {
        if (tid < o) { r1[tid] += r1[tid + o]; r2[tid] += r2[tid + o]; r3[tid] += r3[tid + o]; }
        __syncthreads();
    }
    if (tid == 0) {
        double res = r1[0] / 16777216.0 + r2[0] / 16777216.0 + r3[0] / 40960.0;
        out[0] = (float)res;
    }
}

// ---------------------------------------------------------------------------
extern "C" void kernel_launch(void* const* d_in, const int* in_sizes, int n_in,
                              void* d_out, int out_size) {
    const float* t   = (const float*)d_in[0];
    const float* xt  = (const float*)d_in[1];
    const float* pp  = (const float*)d_in[2];
    const float* pt  = (const float*)d_in[3];
    const float* icp = (const float*)d_in[4];
    const float* ict = (const float*)d_in[5];
    const float* W1  = (const float*)d_in[6];
    const float* b1  = (const float*)d_in[7];
    const float* W2  = (const float*)d_in[8];
    const float* b2  = (const float*)d_in[9];

    build_table<<<(TBL + 1 + 255) / 256, 256>>>(W1, b1, W2, b2);
    main_kernel<<<NBLK, TPB>>>(t, xt, pp);
    finalize<<<1, 256>>>(pp, pt, icp, ict, (float*)d_out);
}

// round 2
// speedup vs baseline: 1.3816x; 1.3816x over previous
#include <cuda_runtime.h>
#include <cuda_fp16.h>

#define B_    256
#define T_    4096
#define TWO_N 16
#define H_    64
#define P_    144
#define TBL   1024
#define TPB   256
#define CHUNKS (T_/TPB)      // 16
#define NBLK  (B_*CHUNKS)    // 4096

// Lookup table row i: 16 half2 = (lat_k, dlat_k) pairs at t = i/TBL.  64 B/row.
__device__ __half2 g_table[TBL + 1][16];
__device__ float g_pd[NBLK];
__device__ float g_pp[NBLK];

// ---------------------------------------------------------------------------
// Kernel 1: tabulate latent(t) and d latent/dt. Fully parallel:
// 4 table entries per 256-thread block; 64 threads per entry compute tanh in
// parallel, then 16 threads per entry do the 16 output dot-products.
// ---------------------------------------------------------------------------
__global__ __launch_bounds__(256) void build_table(
    const float* __restrict__ W1, const float* __restrict__ b1,
    const float* __restrict__ W2, const float* __restrict__ b2) {

    __shared__ float s_th[4][64];
    __shared__ float s_dh[4][64];

    const int tid = threadIdx.x;
    const int el  = tid >> 6;            // entry-local 0..3
    const int j   = tid & 63;            // hidden unit
    const int e   = blockIdx.x * 4 + el; // table entry

    if (e <= TBL) {
        float tv = (float)e / (float)TBL;
        float w1 = __ldg(W1 + j);
        float u  = fmaf(tv, w1, __ldg(b1 + j));
        float th = tanhf(u);
        s_th[el][j] = th;
        s_dh[el][j] = w1 * (1.f - th * th);
    }
    __syncthreads();

    if (e <= TBL && j < 16) {
        const int k = j;
        float lat  = __ldg(b2 + k);
        float dlat = 0.f;
#pragma unroll
        for (int jj = 0; jj < H_; jj++) {
            float w2 = __ldg(W2 + jj * 16 + k);
            lat  = fmaf(s_th[el][jj], w2, lat);
            dlat = fmaf(s_dh[el][jj], w2, dlat);
        }
        g_table[e][k] = __floats2half2_rn(lat, dlat);
    }
}

// ---------------------------------------------------------------------------
// Kernel 2: main loss kernel. One block = (batch b, 256 t's).
// Phase A: 16 lanes/t cooperatively gather+lerp the two 64-B table rows.
// Phase B: t-parallel compute of data + physics loss; block reduction.
// ---------------------------------------------------------------------------
__global__ __launch_bounds__(TPB) void main_kernel(
    const float* __restrict__ t_in,
    const float* __restrict__ x_target,
    const float* __restrict__ params) {

    __shared__ float s_t[TPB];
    __shared__ float s_stage[TPB][33];   // padded stride 33 -> conflict-free
    __shared__ float s_par[P_];          // [0..7]=g, [8..15]=mu, [16..79]=Pi, [80..143]=Gamma
    __shared__ float s_rd[TPB / 32], s_rp[TPB / 32];

    const int tid   = threadIdx.x;
    const int b     = blockIdx.x >> 4;   // / CHUNKS
    const int chunk = blockIdx.x & (CHUNKS - 1);
    const int t0    = chunk * TPB;

    s_t[tid] = __ldg(t_in + (size_t)b * T_ + t0 + tid);
    if (tid < P_) s_par[tid] = __ldg(params + (size_t)b * P_ + tid);
    __syncthreads();

    // ---- Phase A: staged gather (fp16 table, fp32 lerp) ----
    const int kk = tid & 15;     // component index 0..15
    const int ts = tid >> 4;     // base t within the 16-wide groups
#pragma unroll
    for (int it = 0; it < 16; ++it) {
        int tcur = ts + it * 16;
        float tv = s_t[tcur];
        float p  = tv * (float)TBL;
        int   i  = (int)p;
        i = max(0, min(i, TBL - 1));
        float f = p - (float)i;
        float2 lo = __half22float2(__ldg(&g_table[i][kk]));
        float2 hi = __half22float2(__ldg(&g_table[i + 1][kk]));
        s_stage[tcur][2 * kk]     = fmaf(f, hi.x - lo.x, lo.x);
        s_stage[tcur][2 * kk + 1] = fmaf(f, hi.y - lo.y, lo.y);
    }
    __syncthreads();

    // ---- Phase B: per-t compute ----
    float lat[16], dlat[16];
#pragma unroll
    for (int k = 0; k < 16; k++) {
        lat[k]  = s_stage[tid][2 * k];
        dlat[k] = s_stage[tid][2 * k + 1];
    }

    // observables: a = lat[0:8] ; x = relu(q - mu), q = lat[8:16]
    float x[8], dxv[8];
#pragma unroll
    for (int k = 0; k < 8; k++) {
        float s = lat[8 + k] - s_par[8 + k];
        x[k]   = fmaxf(s, 0.f);
        dxv[k] = (s > 0.f) ? dlat[8 + k] : 0.f;   // JVP of relu
    }

    float acc_d = 0.f, acc_p = 0.f;

    // data loss: (state - x_target)^2, x_target layout (B, 16, T)
    const float* xt = x_target + (size_t)b * TWO_N * T_ + t0 + tid;
#pragma unroll
    for (int k = 0; k < 16; k++) {
        float st = (k < 8) ? lat[k] : x[k - 8];
        float d  = st - __ldg(xt + (size_t)k * T_);
        acc_d = fmaf(d, d, acc_d);
    }

    // physics loss: da = g + Pi@x - a ; dx = (Gamma@a) * (mu - x)
#pragma unroll
    for (int k = 0; k < 8; k++) {
        float pix = 0.f, ga = 0.f;
#pragma unroll
        for (int j = 0; j < 8; j++) {
            pix = fmaf(s_par[16 + k * 8 + j], x[j],   pix);
            ga  = fmaf(s_par[80 + k * 8 + j], lat[j], ga);
        }
        float d1 = dlat[k] - (s_par[k] + pix - lat[k]);
        acc_p = fmaf(d1, d1, acc_p);
        float d2 = dxv[k] - ga * (s_par[8 + k] - x[k]);
        acc_p = fmaf(d2, d2, acc_p);
    }

    // ---- block reduction (deterministic tree) ----
#pragma unroll
    for (int o = 16; o; o >>= 1) {
        acc_d += __shfl_down_sync(0xffffffffu, acc_d, o);
        acc_p += __shfl_down_sync(0xffffffffu, acc_p, o);
    }
    const int lane = tid & 31, wid = tid >> 5;
    if (lane == 0) { s_rd[wid] = acc_d; s_rp[wid] = acc_p; }
    __syncthreads();
    if (tid == 0) {
        float sd = 0.f, sp = 0.f;
#pragma unroll
        for (int i = 0; i < TPB / 32; i++) { sd += s_rd[i]; sp += s_rp[i]; }
        g_pd[blockIdx.x] = sd;
        g_pp[blockIdx.x] = sp;
    }
}

// ---------------------------------------------------------------------------
// Kernel 3: deterministic finalize. Sums block partials (double), adds the
// tiny supervised loss, writes the scalar.
// ---------------------------------------------------------------------------
__global__ void finalize(const float* __restrict__ pp, const float* __restrict__ pt,
                         const float* __restrict__ icp, const float* __restrict__ ict,
                         float* __restrict__ out) {
    const int tid = threadIdx.x;
    double sd = 0.0, sp = 0.0, ss = 0.0;
    for (int i = tid; i < NBLK; i += 256) {
        sd += (double)g_pd[i];
        sp += (double)g_pp[i];
    }
    for (int i = tid; i < B_ * 160; i += 256) {
        int b = i / 160, r = i % 160;
        float d;
        if (r < P_) d = __ldg(pp + b * P_ + r) - __ldg(pt + b * P_ + r);
        else        d = __ldg(icp + b * 16 + (r - P_)) - __ldg(ict + b * 16 + (r - P_));
        ss += (double)d * (double)d;
    }
    __shared__ double r1[256], r2[256], r3[256];
    r1[tid] = sd; r2[tid] = sp; r3[tid] = ss;
    __syncthreads();
    for (int o = 128; o; o >>= 1) {
        if (tid < o) { r1[tid] += r1[tid + o]; r2[tid] += r2[tid + o]; r3[tid] += r3[tid + o]; }
        __syncthreads();
    }
    if (tid == 0) {
        double res = r1[0] / 16777216.0 + r2[0] / 16777216.0 + r3[0] / 40960.0;
        out[0] = (float)res;
    }
}

// ---------------------------------------------------------------------------
extern "C" void kernel_launch(void* const* d_in, const int* in_sizes, int n_in,
                              void* d_out, int out_size) {
    const float* t   = (const float*)d_in[0];
    const float* xt  = (const float*)d_in[1];
    const float* pp  = (const float*)d_in[2];
    const float* pt  = (const float*)d_in[3];
    const float* icp = (const float*)d_in[4];
    const float* ict = (const float*)d_in[5];
    const float* W1  = (const float*)d_in[6];
    const float* b1  = (const float*)d_in[7];
    const float* W2  = (const float*)d_in[8];
    const float* b2  = (const float*)d_in[9];

    build_table<<<(TBL + 1 + 3) / 4, 256>>>(W1, b1, W2, b2);
    main_kernel<<<NBLK, TPB>>>(t, xt, pp);
    finalize<<<1, 256>>>(pp, pt, icp, ict, (float*)d_out);
}

// round 3
// speedup vs baseline: 1.9275x; 1.3951x over previous
#include <cuda_runtime.h>

#define B_    256
#define T_    4096
#define TWO_N 16
#define H_    64
#define P_    144
#define TBL   1024
#define TPB   256
#define CHUNKS (T_/TPB)      // 16
#define NBLK  (B_*CHUNKS)    // 4096
#define SUPB  40             // supervised-loss blocks (40*1024 = 40960 elems)

// fp32 table row i: 32 floats = (lat_0,dlat_0,...,lat_15,dlat_15) at t=i/TBL. 128 B/row.
__device__ float g_table[TBL + 1][32];
__device__ float g_pd[NBLK];
__device__ float g_pp[NBLK];
__device__ float g_sup[SUPB];

// ---------------------------------------------------------------------------
// Kernel 1: tabulate latent/dlatent (4 entries per block, 64 threads each),
// and blocks 0..39 additionally reduce the supervised loss (1024 elems each).
// ---------------------------------------------------------------------------
__global__ __launch_bounds__(256) void build_table(
    const float* __restrict__ W1, const float* __restrict__ b1,
    const float* __restrict__ W2, const float* __restrict__ b2,
    const float* __restrict__ pp, const float* __restrict__ pt,
    const float* __restrict__ icp, const float* __restrict__ ict) {

    __shared__ float s_th[4][64];
    __shared__ float s_dh[4][64];
    __shared__ float s_red[8];

    const int tid = threadIdx.x;
    const int el  = tid >> 6;            // entry-local 0..3
    const int j   = tid & 63;            // hidden unit
    const int e   = blockIdx.x * 4 + el; // table entry

    if (e <= TBL) {
        float tv = (float)e / (float)TBL;
        float w1 = __ldg(W1 + j);
        float u  = fmaf(tv, w1, __ldg(b1 + j));
        float th = tanhf(u);
        s_th[el][j] = th;
        s_dh[el][j] = w1 * (1.f - th * th);
    }
    __syncthreads();

    if (e <= TBL && j < 16) {
        const int k = j;
        float lat  = __ldg(b2 + k);
        float dlat = 0.f;
#pragma unroll
        for (int jj = 0; jj < H_; jj++) {
            float w2 = __ldg(W2 + jj * 16 + k);
            lat  = fmaf(s_th[el][jj], w2, lat);
            dlat = fmaf(s_dh[el][jj], w2, dlat);
        }
        g_table[e][2 * k]     = lat;
        g_table[e][2 * k + 1] = dlat;
    }

    // ---- supervised loss partials (blocks 0..39) ----
    if (blockIdx.x < SUPB) {
        const int ebase = blockIdx.x * 1024 + tid * 4;   // < 40960
        float4 a, t4;
        if (ebase < B_ * P_) {           // 36864, block-aligned split
            a  = __ldg((const float4*)(pp + ebase));
            t4 = __ldg((const float4*)(pt + ebase));
        } else {
            int r = ebase - B_ * P_;
            a  = __ldg((const float4*)(icp + r));
            t4 = __ldg((const float4*)(ict + r));
        }
        float dx = a.x - t4.x, dy = a.y - t4.y, dz = a.z - t4.z, dw = a.w - t4.w;
        float s = fmaf(dx, dx, fmaf(dy, dy, fmaf(dz, dz, dw * dw)));
#pragma unroll
        for (int o = 16; o; o >>= 1) s += __shfl_down_sync(0xffffffffu, s, o);
        if ((tid & 31) == 0) s_red[tid >> 5] = s;
        __syncthreads();
        if (tid == 0) {
            float tot = 0.f;
#pragma unroll
            for (int i = 0; i < 8; i++) tot += s_red[i];
            g_sup[blockIdx.x] = tot;
        }
    }
}

// ---------------------------------------------------------------------------
// Kernel 2: main loss kernel. One block = (batch b, 256 t's).
// Phase A: 8 lanes/t, one LDG.128 each covers a full 128-B table row.
// Phase B: t-parallel compute; block reduction.
// ---------------------------------------------------------------------------
__global__ __launch_bounds__(TPB) void main_kernel(
    const float* __restrict__ t_in,
    const float* __restrict__ x_target,
    const float* __restrict__ params) {

    __shared__ float s_t[TPB];
    __shared__ float s_stage[TPB][40];   // 32 used, 160-B rows (16B-aligned, padded)
    __shared__ float s_par[P_];
    __shared__ float s_rd[TPB / 32], s_rp[TPB / 32];

    const int tid   = threadIdx.x;
    const int b     = blockIdx.x >> 4;
    const int chunk = blockIdx.x & (CHUNKS - 1);
    const int t0    = chunk * TPB;

    s_t[tid] = __ldg(t_in + (size_t)b * T_ + t0 + tid);
    if (tid < P_) s_par[tid] = __ldg(params + (size_t)b * P_ + tid);
    __syncthreads();

    // ---- Phase A: cooperative vector gather + lerp ----
    const int kk = tid & 7;      // float4 slot (components 2kk, 2kk+1)
    const int ts = tid >> 3;     // base t (0..31)
#pragma unroll
    for (int pass = 0; pass < 8; ++pass) {
        int tcur = ts + pass * 32;
        float tv = s_t[tcur];
        float p  = tv * (float)TBL;
        int   i  = (int)p;
        i = max(0, min(i, TBL - 1));
        float f = p - (float)i;
        const float4* r0 = (const float4*)g_table[i] + kk;
        float4 lo = __ldg(r0);
        float4 hi = __ldg(r0 + 8);       // next row = +32 floats
        float4 res;
        res.x = fmaf(f, hi.x - lo.x, lo.x);
        res.y = fmaf(f, hi.y - lo.y, lo.y);
        res.z = fmaf(f, hi.z - lo.z, lo.z);
        res.w = fmaf(f, hi.w - lo.w, lo.w);
        *(float4*)&s_stage[tcur][kk * 4] = res;
    }
    __syncthreads();

    // ---- Phase B: per-t compute ----
    float lat[16], dlat[16];
#pragma unroll
    for (int jj = 0; jj < 8; jj++) {
        float4 v = *(const float4*)&s_stage[tid][jj * 4];
        lat[2 * jj]      = v.x;
        dlat[2 * jj]     = v.y;
        lat[2 * jj + 1]  = v.z;
        dlat[2 * jj + 1] = v.w;
    }

    float x[8], dxv[8];
#pragma unroll
    for (int k = 0; k < 8; k++) {
        float s = lat[8 + k] - s_par[8 + k];
        x[k]   = fmaxf(s, 0.f);
        dxv[k] = (s > 0.f) ? dlat[8 + k] : 0.f;
    }

    float acc_d = 0.f, acc_p = 0.f;

    const float* xt = x_target + (size_t)b * TWO_N * T_ + t0 + tid;
#pragma unroll
    for (int k = 0; k < 16; k++) {
        float st = (k < 8) ? lat[k] : x[k - 8];
        float d  = st - __ldg(xt + (size_t)k * T_);
        acc_d = fmaf(d, d, acc_d);
    }

#pragma unroll
    for (int k = 0; k < 8; k++) {
        float pix = 0.f, ga = 0.f;
#pragma unroll
        for (int j = 0; j < 8; j++) {
            pix = fmaf(s_par[16 + k * 8 + j], x[j],   pix);
            ga  = fmaf(s_par[80 + k * 8 + j], lat[j], ga);
        }
        float d1 = dlat[k] - (s_par[k] + pix - lat[k]);
        acc_p = fmaf(d1, d1, acc_p);
        float d2 = dxv[k] - ga * (s_par[8 + k] - x[k]);
        acc_p = fmaf(d2, d2, acc_p);
    }

#pragma unroll
    for (int o = 16; o; o >>= 1) {
        acc_d += __shfl_down_sync(0xffffffffu, acc_d, o);
        acc_p += __shfl_down_sync(0xffffffffu, acc_p, o);
    }
    const int lane = tid & 31, wid = tid >> 5;
    if (lane == 0) { s_rd[wid] = acc_d; s_rp[wid] = acc_p; }
    __syncthreads();
    if (tid == 0) {
        float sd = 0.f, sp = 0.f;
#pragma unroll
        for (int i = 0; i < TPB / 32; i++) { sd += s_rd[i]; sp += s_rp[i]; }
        g_pd[blockIdx.x] = sd;
        g_pp[blockIdx.x] = sp;
    }
}

// ---------------------------------------------------------------------------
// Kernel 3: finalize — deterministic double sums of tiny partial arrays.
// ---------------------------------------------------------------------------
__global__ void finalize(float* __restrict__ out) {
    const int tid = threadIdx.x;
    double sd = 0.0, sp = 0.0;
    for (int i = tid; i < NBLK; i += 256) {
        sd += (double)g_pd[i];
        sp += (double)g_pp[i];
    }
    double ss = (tid < SUPB) ? (double)g_sup[tid] : 0.0;
    __shared__ double r1[256], r2[256], r3[256];
    r1[tid] = sd; r2[tid] = sp; r3[tid] = ss;
    __syncthreads();
    for (int o = 128; o; o >>= 1) {
        if (tid < o) { r1[tid] += r1[tid + o]; r2[tid] += r2[tid + o]; r3[tid] += r3[tid + o]; }
        __syncthreads();
    }
    if (tid == 0) {
        double res = (r1[0] + r2[0]) / 16777216.0 + r3[0] / 40960.0;
        out[0] = (float)res;
    }
}

// ---------------------------------------------------------------------------
extern "C" void kernel_launch(void* const* d_in, const int* in_sizes, int n_in,
                              void* d_out, int out_size) {
    const float* t   = (const float*)d_in[0];
    const float* xt  = (const float*)d_in[1];
    const float* pp  = (const float*)d_in[2];
    const float* pt  = (const float*)d_in[3];
    const float* icp = (const float*)d_in[4];
    const float* ict = (const float*)d_in[5];
    const float* W1  = (const float*)d_in[6];
    const float* b1  = (const float*)d_in[7];
    const float* W2  = (const float*)d_in[8];
    const float* b2  = (const float*)d_in[9];

    build_table<<<(TBL + 1 + 3) / 4, 256>>>(W1, b1, W2, b2, pp, pt, icp, ict);
    main_kernel<<<NBLK, TPB>>>(t, xt, pp);
    finalize<<<1, 256>>>((float*)d_out);
}

// round 4
// speedup vs baseline: 2.2456x; 1.1651x over previous
#include <cuda_runtime.h>

#define B_    256
#define T_    4096
#define TWO_N 16
#define H_    64
#define P_    144
#define TBL   256
#define TPB   256
#define CHUNKS (T_/TPB)      // 16
#define NBLK  (B_*CHUNKS)    // 4096
#define SUPB  40             // supervised-loss blocks (40*1024 = 40960 elems)
#define PAD   36             // stage row stride (floats): 4*tid mod 32 covers all banks

// fp32 table row i: 32 floats = (lat_0,dlat_0,...,lat_15,dlat_15) at t=i/TBL. 128 B/row.
// Total (TBL+1)*128 B = 32.9 KB -> L1-resident on every SM.
__device__ float g_table[TBL + 1][32];
__device__ float g_pd[NBLK];
__device__ float g_pp[NBLK];
__device__ float g_sup[SUPB];

// ---------------------------------------------------------------------------
// Kernel 1: tabulate latent/dlatent. 4 entries per 256-thread block; 64
// threads per entry: tanh j-parallel, then each (k, quarter) pair sums 16
// terms, reduced via shfl + smem. Blocks 0..SUPB-1 also fold the supervised
// loss.
// ---------------------------------------------------------------------------
__global__ __launch_bounds__(256) void build_table(
    const float* __restrict__ W1, const float* __restrict__ b1,
    const float* __restrict__ W2, const float* __restrict__ b2,
    const float* __restrict__ pp, const float* __restrict__ pt,
    const float* __restrict__ icp, const float* __restrict__ ict) {

    __shared__ float s_th[4][64];
    __shared__ float s_dh[4][64];
    __shared__ float s_x[4][16], s_y[4][16];
    __shared__ float s_red[8];

    const int tid = threadIdx.x;
    const int el  = tid >> 6;            // entry-local 0..3
    const int j   = tid & 63;            // hidden unit
    const int e   = blockIdx.x * 4 + el; // table entry

    if (e <= TBL) {
        float tv = (float)e / (float)TBL;
        float w1 = __ldg(W1 + j);
        float u  = fmaf(tv, w1, __ldg(b1 + j));
        float th = tanhf(u);
        s_th[el][j] = th;
        s_dh[el][j] = w1 * (1.f - th * th);
    }
    __syncthreads();

    // dot products: k = tid&15, quarter h = (tid>>4)&3 sums jj in [16h,16h+16)
    {
        const int k = tid & 15;
        const int h = (tid >> 4) & 3;
        const int wi = (tid >> 5) & 1;   // warp within entry
        float lat = 0.f, dlat = 0.f;
        if (e <= TBL) {
#pragma unroll
            for (int q = 0; q < 16; q++) {
                int jj = h * 16 + q;
                float w2 = __ldg(W2 + jj * 16 + k);
                lat  = fmaf(s_th[el][jj], w2, lat);
                dlat = fmaf(s_dh[el][jj], w2, dlat);
            }
        }
        lat  += __shfl_xor_sync(0xffffffffu, lat,  16);
        dlat += __shfl_xor_sync(0xffffffffu, dlat, 16);
        if (wi == 1 && (tid & 31) < 16) { s_x[el][k] = lat; s_y[el][k] = dlat; }
        __syncthreads();
        if (e <= TBL && wi == 0 && (tid & 31) < 16) {
            g_table[e][2 * k]     = lat + s_x[el][k] + __ldg(b2 + k);
            g_table[e][2 * k + 1] = dlat + s_y[el][k];
        }
    }

    // ---- supervised loss partials (blocks 0..SUPB-1) ----
    if (blockIdx.x < SUPB) {
        const int ebase = blockIdx.x * 1024 + tid * 4;   // < 40960
        float4 a, t4;
        if (ebase < B_ * P_) {           // 36864, block-aligned split
            a  = __ldg((const float4*)(pp + ebase));
            t4 = __ldg((const float4*)(pt + ebase));
        } else {
            int r = ebase - B_ * P_;
            a  = __ldg((const float4*)(icp + r));
            t4 = __ldg((const float4*)(ict + r));
        }
        float dx = a.x - t4.x, dy = a.y - t4.y, dz = a.z - t4.z, dw = a.w - t4.w;
        float s = fmaf(dx, dx, fmaf(dy, dy, fmaf(dz, dz, dw * dw)));
#pragma unroll
        for (int o = 16; o; o >>= 1) s += __shfl_down_sync(0xffffffffu, s, o);
        if ((tid & 31) == 0) s_red[tid >> 5] = s;
        __syncthreads();
        if (tid == 0) {
            float tot = 0.f;
#pragma unroll
            for (int i = 0; i < 8; i++) tot += s_red[i];
            g_sup[blockIdx.x] = tot;
        }
    }
}

// ---------------------------------------------------------------------------
// Kernel 2: main loss kernel. One block = (batch b, 256 t's).
// Phase A: 8 lanes/t, one LDG.128 each covers a full 128-B table row (L1 hit).
// Phase B: t-parallel compute; block reduction.
// ---------------------------------------------------------------------------
__global__ __launch_bounds__(TPB) void main_kernel(
    const float* __restrict__ t_in,
    const float* __restrict__ x_target,
    const float* __restrict__ params) {

    __shared__ float s_t[TPB];
    __shared__ float s_stage[TPB][PAD];
    __shared__ float s_par[P_];
    __shared__ float s_rd[TPB / 32], s_rp[TPB / 32];

    const int tid   = threadIdx.x;
    const int b     = blockIdx.x >> 4;
    const int chunk = blockIdx.x & (CHUNKS - 1);
    const int t0    = chunk * TPB;

    s_t[tid] = __ldg(t_in + (size_t)b * T_ + t0 + tid);
    if (tid < P_) s_par[tid] = __ldg(params + (size_t)b * P_ + tid);
    __syncthreads();

    // ---- Phase A: cooperative vector gather + lerp ----
    const int kk = tid & 7;      // float4 slot (components 2kk, 2kk+1)
    const int ts = tid >> 3;     // base t (0..31)
#pragma unroll
    for (int pass = 0; pass < 8; ++pass) {
        int tcur = ts + pass * 32;
        float tv = s_t[tcur];
        float p  = tv * (float)TBL;
        int   i  = (int)p;
        i = max(0, min(i, TBL - 1));
        float f = p - (float)i;
        const float4* r0 = (const float4*)g_table[i] + kk;
        float4 lo = __ldg(r0);
        float4 hi = __ldg(r0 + 8);       // next row = +32 floats
        float4 res;
        res.x = fmaf(f, hi.x - lo.x, lo.x);
        res.y = fmaf(f, hi.y - lo.y, lo.y);
        res.z = fmaf(f, hi.z - lo.z, lo.z);
        res.w = fmaf(f, hi.w - lo.w, lo.w);
        *(float4*)&s_stage[tcur][kk * 4] = res;
    }
    __syncthreads();

    // ---- Phase B: per-t compute ----
    float lat[16], dlat[16];
#pragma unroll
    for (int jj = 0; jj < 8; jj++) {
        float4 v = *(const float4*)&s_stage[tid][jj * 4];
        lat[2 * jj]      = v.x;
        dlat[2 * jj]     = v.y;
        lat[2 * jj + 1]  = v.z;
        dlat[2 * jj + 1] = v.w;
    }

    float x[8], dxv[8];
#pragma unroll
    for (int k = 0; k < 8; k++) {
        float s = lat[8 + k] - s_par[8 + k];
        x[k]   = fmaxf(s, 0.f);
        dxv[k] = (s > 0.f) ? dlat[8 + k] : 0.f;
    }

    float acc_d = 0.f, acc_p = 0.f;

    const float* xt = x_target + (size_t)b * TWO_N * T_ + t0 + tid;
#pragma unroll
    for (int k = 0; k < 16; k++) {
        float st = (k < 8) ? lat[k] : x[k - 8];
        float d  = st - __ldg(xt + (size_t)k * T_);
        acc_d = fmaf(d, d, acc_d);
    }

#pragma unroll
    for (int k = 0; k < 8; k++) {
        float pix = 0.f, ga = 0.f;
#pragma unroll
        for (int j = 0; j < 8; j++) {
            pix = fmaf(s_par[16 + k * 8 + j], x[j],   pix);
            ga  = fmaf(s_par[80 + k * 8 + j], lat[j], ga);
        }
        float d1 = dlat[k] - (s_par[k] + pix - lat[k]);
        acc_p = fmaf(d1, d1, acc_p);
        float d2 = dxv[k] - ga * (s_par[8 + k] - x[k]);
        acc_p = fmaf(d2, d2, acc_p);
    }

#pragma unroll
    for (int o = 16; o; o >>= 1) {
        acc_d += __shfl_down_sync(0xffffffffu, acc_d, o);
        acc_p += __shfl_down_sync(0xffffffffu, acc_p, o);
    }
    const int lane = tid & 31, wid = tid >> 5;
    if (lane == 0) { s_rd[wid] = acc_d; s_rp[wid] = acc_p; }
    __syncthreads();
    if (tid == 0) {
        float sd = 0.f, sp = 0.f;
#pragma unroll
        for (int i = 0; i < TPB / 32; i++) { sd += s_rd[i]; sp += s_rp[i]; }
        g_pd[blockIdx.x] = sd;
        g_pp[blockIdx.x] = sp;
    }
}

// ---------------------------------------------------------------------------
// Kernel 3: finalize — deterministic double sums of tiny partial arrays.
// ---------------------------------------------------------------------------
__global__ void finalize(float* __restrict__ out) {
    const int tid = threadIdx.x;
    double sd = 0.0, sp = 0.0;
    for (int i = tid; i < NBLK; i += 256) {
        sd += (double)g_pd[i];
        sp += (double)g_pp[i];
    }
    double ss = (tid < SUPB) ? (double)g_sup[tid] : 0.0;
    __shared__ double r1[256], r2[256], r3[256];
    r1[tid] = sd; r2[tid] = sp; r3[tid] = ss;
    __syncthreads();
    for (int o = 128; o; o >>= 1) {
        if (tid < o) { r1[tid] += r1[tid + o]; r2[tid] += r2[tid + o]; r3[tid] += r3[tid + o]; }
        __syncthreads();
    }
    if (tid == 0) {
        double res = (r1[0] + r2[0]) / 16777216.0 + r3[0] / 40960.0;
        out[0] = (float)res;
    }
}

// ---------------------------------------------------------------------------
extern "C" void kernel_launch(void* const* d_in, const int* in_sizes, int n_in,
                              void* d_out, int out_size) {
    const float* t   = (const float*)d_in[0];
    const float* xt  = (const float*)d_in[1];
    const float* pp  = (const float*)d_in[2];
    const float* pt  = (const float*)d_in[3];
    const float* icp = (const float*)d_in[4];
    const float* ict = (const float*)d_in[5];
    const float* W1  = (const float*)d_in[6];
    const float* b1  = (const float*)d_in[7];
    const float* W2  = (const float*)d_in[8];
    const float* b2  = (const float*)d_in[9];

    build_table<<<(TBL + 1 + 3) / 4, 256>>>(W1, b1, W2, b2, pp, pt, icp, ict);
    main_kernel<<<NBLK, TPB>>>(t, xt, pp);
    finalize<<<1, 256>>>((float*)d_out);
}